// round 1
// baseline (speedup 1.0000x reference)
#include <cuda_runtime.h>

#define B_TOTAL  8192
#define T_STEPS  512
#define HID      128
#define BM       64      // batch rows per CTA
#define PITCH    132     // 128 h + 2 x + 2 zero-pad (uniform float4 k-loop)
#define NTHREADS 256
#define ALPHA_C  0.2f
#define BETA_C   0.7f

// tanh(x) = 1 - 2/(exp(2x)+1); MUFU.EX2 + MUFU.RCP based, ~1e-7 abs err.
__device__ __forceinline__ float tanh_fast(float x) {
    float e = __expf(2.0f * x);
    return 1.0f - __fdividef(2.0f, e + 1.0f);
}

extern __shared__ float smem[];

__global__ __launch_bounds__(NTHREADS, 1)
void rnn_kernel(const float* __restrict__ input,   // (B, T, 2)
                const float* __restrict__ W_rec,   // (130, 128)
                const float* __restrict__ b_rec,   // (128)
                const float* __restrict__ W_out,   // (128, 1)
                const float* __restrict__ b_out,   // (1)
                float* __restrict__ out)           // (B)
{
    float* sW = smem;                 // [PITCH][HID], k-major: sW[k*128+n]
    float* sA = smem + PITCH * HID;   // [BM][PITCH], conc = [h(128) | x(2) | pad(2)]

    const int tid = threadIdx.x;
    const int cg  = tid & 31;   // lane = column group (4 cols)
    const int rg  = tid >> 5;   // warp  = row group (8 rows)
    const int n0  = cg * 4;
    const int rowBase = rg * 8;
    const int bBase   = blockIdx.x * BM;

    // Load W reordered: k<128 -> W_rec[k+2] (hidden), k=128/129 -> W_rec[0/1] (x), k>=130 -> 0
    for (int idx = tid; idx < PITCH * HID; idx += NTHREADS) {
        int k = idx >> 7;
        int n = idx & 127;
        float v;
        if      (k < 128) v = W_rec[(k + 2) * HID + n];
        else if (k < 130) v = W_rec[(k - 128) * HID + n];
        else              v = 0.0f;
        sW[idx] = v;
    }
    // Zero state tile (h_{-1} = 0, pads = 0)
    for (int idx = tid; idx < BM * PITCH; idx += NTHREADS) sA[idx] = 0.0f;

    float bias[4], wout[4];
    #pragma unroll
    for (int n = 0; n < 4; n++) { bias[n] = b_rec[n0 + n]; wout[n] = W_out[n0 + n]; }
    const float bout = b_out[0];

    // Lanes 0..7 of each warp own one batch row each (row = rowBase + cg)
    const int  myLocalRow = rowBase + cg;
    const long long rowOff = (long long)(bBase + myLocalRow) * T_STEPS * 2;

    float  sig2 = 0.0f, prevx0 = 0.0f;
    float2 xcur = make_float2(0.0f, 0.0f);
    if (cg < 8) {
        xcur = *(const float2*)(input + rowOff);       // x_0
        sA[myLocalRow * PITCH + 128] = xcur.x;
        sA[myLocalRow * PITCH + 129] = xcur.y;
    }
    __syncthreads();

    const float4* A4 = (const float4*)sA;   // pitch in float4 = 33
    const float4* W4 = (const float4*)sW;

    for (int t = 0; t < T_STEPS; ++t) {
        // Prefetch x_{t+1} (latency hidden under the ~16k-cycle k-loop)
        float2 xnext = make_float2(0.0f, 0.0f);
        if (cg < 8 && t + 1 < T_STEPS)
            xnext = *(const float2*)(input + rowOff + (long long)(t + 1) * 2);

        float acc[8][4];
        #pragma unroll
        for (int m = 0; m < 8; m++) {
            acc[m][0] = bias[0]; acc[m][1] = bias[1];
            acc[m][2] = bias[2]; acc[m][3] = bias[3];
        }

        // GEMM: acc[m][n] += sum_k conc[m][k] * W'[k][n]   (k = 0..131, pads are 0)
        #pragma unroll 3
        for (int kq = 0; kq < PITCH / 4; ++kq) {
            float4 a[8];
            #pragma unroll
            for (int m = 0; m < 8; m++)
                a[m] = A4[(rowBase + m) * (PITCH / 4) + kq];   // warp-broadcast
            #pragma unroll
            for (int kk = 0; kk < 4; kk++) {
                float4 w = W4[(((kq * 4 + kk) * HID) + n0) >> 2];
                #pragma unroll
                for (int m = 0; m < 8; m++) {
                    float av = (kk == 0) ? a[m].x : (kk == 1) ? a[m].y
                             : (kk == 2) ? a[m].z : a[m].w;
                    acc[m][0] = fmaf(av, w.x, acc[m][0]);
                    acc[m][1] = fmaf(av, w.y, acc[m][1]);
                    acc[m][2] = fmaf(av, w.z, acc[m][2]);
                    acc[m][3] = fmaf(av, w.w, acc[m][3]);
                }
            }
        }

        // tanh + omega partials
        float part[8];
        #pragma unroll
        for (int m = 0; m < 8; m++) {
            acc[m][0] = tanh_fast(acc[m][0]);
            acc[m][1] = tanh_fast(acc[m][1]);
            acc[m][2] = tanh_fast(acc[m][2]);
            acc[m][3] = tanh_fast(acc[m][3]);
            part[m] = acc[m][0] * wout[0] + acc[m][1] * wout[1]
                    + acc[m][2] * wout[2] + acc[m][3] * wout[3];
        }
        // Butterfly reduce omega across the 32 column-groups (per row)
        #pragma unroll
        for (int m = 0; m < 8; m++) {
            part[m] += __shfl_xor_sync(0xffffffffu, part[m], 16);
            part[m] += __shfl_xor_sync(0xffffffffu, part[m], 8);
            part[m] += __shfl_xor_sync(0xffffffffu, part[m], 4);
            part[m] += __shfl_xor_sync(0xffffffffu, part[m], 2);
            part[m] += __shfl_xor_sync(0xffffffffu, part[m], 1);
        }

        __syncthreads();   // all reads of sA done before overwrite

        // Write h_t back into conc tile
        #pragma unroll
        for (int m = 0; m < 8; m++) {
            float4 h = make_float4(acc[m][0], acc[m][1], acc[m][2], acc[m][3]);
            *(float4*)&sA[(rowBase + m) * PITCH + n0] = h;
        }

        if (cg < 8) {
            float om = 0.0f;
            #pragma unroll
            for (int m = 0; m < 8; m++) if (cg == m) om = part[m];
            // sig2_t = sig2*beta + resid^2*alpha + omega_t, resid = x_{t-1}[0]
            sig2 = sig2 * BETA_C + prevx0 * prevx0 * ALPHA_C + (om + bout);
            prevx0 = xcur.x;
            sA[myLocalRow * PITCH + 128] = xnext.x;
            sA[myLocalRow * PITCH + 129] = xnext.y;
            xcur = xnext;
        }
        __syncthreads();   // writes visible before next step's reads
    }

    if (cg < 8) out[bBase + myLocalRow] = sig2;
}

extern "C" void kernel_launch(void* const* d_in, const int* in_sizes, int n_in,
                              void* d_out, int out_size) {
    const float* input = (const float*)d_in[0];
    const float* W_rec = (const float*)d_in[1];
    const float* b_rec = (const float*)d_in[2];
    const float* W_out = (const float*)d_in[3];
    const float* b_out = (const float*)d_in[4];
    float* out = (float*)d_out;

    const size_t smem_bytes = (size_t)(PITCH * HID + BM * PITCH) * sizeof(float); // 101376
    cudaFuncSetAttribute(rnn_kernel, cudaFuncAttributeMaxDynamicSharedMemorySize,
                         (int)smem_bytes);

    rnn_kernel<<<B_TOTAL / BM, NTHREADS, smem_bytes>>>(input, W_rec, b_rec,
                                                       W_out, b_out, out);
    (void)in_sizes; (void)n_in; (void)out_size;
}